// round 1
// baseline (speedup 1.0000x reference)
#include <cuda_runtime.h>
#include <cuda_bf16.h>
#include <math.h>

// Problem constants (ParQwen3MoeSparseMoeBlock: B=2,S=2048,H=1024,E=64,K=8,F=512,cap=2.0)
#define TOK   4096        // B*S
#define HD    1024
#define NE    64
#define KSEL  8
#define FF    512
#define NA    (TOK*KSEL)  // 32768 assignments
#define CAP   1024        // int(2.0 * NA / NE)

// ---------------- scratch (__device__ globals; no runtime allocation) ----------------
__device__ __align__(16) float g_logits[(size_t)TOK * NE];           // 1 MB
__device__ int   g_sel[NA];
__device__ float g_wgt[NA];
__device__ int   g_rowtok[NE * CAP];
__device__ int   g_slot[NA];
__device__ int   g_cnt[NE];
__device__ __align__(16) float g_act[(size_t)NE * CAP * FF];         // 134 MB
__device__ __align__(16) float g_yb [(size_t)NE * CAP * HD];         // 268 MB

// ---------------- 1) router logits: x[T,H] @ wg[H,E] -> logits[T,E] ----------------
#define RT 8
__global__ __launch_bounds__(256) void router_kernel(const float* __restrict__ x,
                                                     const float* __restrict__ wg) {
    __shared__ __align__(16) float xs[RT][HD];   // 32 KB
    int t0 = blockIdx.x * RT;
    for (int i = threadIdx.x; i < RT * HD / 4; i += 256) {
        int r = i >> 8;            // HD/4 = 256
        int c = (i & 255) << 2;
        *(float4*)&xs[r][c] = *(const float4*)&x[(size_t)(t0 + r) * HD + c];
    }
    __syncthreads();
    int e  = threadIdx.x & 63;
    int tg = threadIdx.x >> 6;     // 0..3 -> tokens tg*2, tg*2+1
    float acc0 = 0.f, acc1 = 0.f;
    #pragma unroll 4
    for (int j = 0; j < HD; ++j) {
        float w = wg[(size_t)j * NE + e];
        acc0 += w * xs[tg * 2 + 0][j];
        acc1 += w * xs[tg * 2 + 1][j];
    }
    g_logits[(size_t)(t0 + tg * 2 + 0) * NE + e] = acc0;
    g_logits[(size_t)(t0 + tg * 2 + 1) * NE + e] = acc1;
}

// ---------------- 2) softmax + top-8 + renormalize ----------------
__global__ void topk_kernel() {
    int t = blockIdx.x * blockDim.x + threadIdx.x;
    if (t >= TOK) return;
    const float* l = g_logits + (size_t)t * NE;
    float m = -INFINITY;
    for (int e = 0; e < NE; ++e) m = fmaxf(m, l[e]);
    float s = 0.f;
    for (int e = 0; e < NE; ++e) s += expf(l[e] - m);

    unsigned long long mask = 0ull;
    float wv[KSEL]; int se[KSEL];
    float wsum = 0.f;
    for (int k = 0; k < KSEL; ++k) {
        float best = -INFINITY; int be = 0;
        for (int e = 0; e < NE; ++e) {
            if ((mask >> e) & 1ull) continue;
            float v = l[e];
            if (v > best) { best = v; be = e; }   // strict > : lowest index on ties
        }
        mask |= (1ull << be);
        float p = expf(best - m) / s;
        wv[k] = p; se[k] = be; wsum += p;
    }
    float inv = 1.f / wsum;
    for (int k = 0; k < KSEL; ++k) {
        g_sel[t * KSEL + k] = se[k];
        g_wgt[t * KSEL + k] = wv[k] * inv;
    }
}

// ---------------- 3) dispatch: stable per-expert positions (block e scans all) ----------------
__global__ __launch_bounds__(256) void dispatch_kernel() {
    int e = blockIdx.x;
    __shared__ int stot[8];
    int tid = threadIdx.x, wid = tid >> 5, lane = tid & 31;
    int run = 0;
    for (int base = 0; base < NA; base += 256) {
        int a = base + tid;
        int m = (g_sel[a] == e) ? 1 : 0;
        unsigned b = __ballot_sync(0xffffffffu, m);
        int wpref = __popc(b & ((1u << lane) - 1u));
        if (lane == 0) stot[wid] = __popc(b);
        __syncthreads();
        int before = 0, total = 0;
        #pragma unroll
        for (int w = 0; w < 8; ++w) {
            int c = stot[w];
            if (w < wid) before += c;
            total += c;
        }
        if (m) {
            int p = run + before + wpref;
            if (p < CAP) {
                g_rowtok[e * CAP + p] = a / KSEL;
                g_slot[a] = e * CAP + p;
            } else {
                g_slot[a] = -1;   // dropped
            }
        }
        run += total;
        __syncthreads();
    }
    if (tid == 0) g_cnt[e] = (run < CAP) ? run : CAP;
}

// ---------------- 4) GEMM-A: act = silu(x@w1) * (x@w3), gathered rows ----------------
#define BM 64
#define BN 64
#define BK 16

__global__ __launch_bounds__(256) void gemm_a_kernel(const float* __restrict__ x,
                                                     const float* __restrict__ w1,
                                                     const float* __restrict__ w3) {
    int e = blockIdx.z;
    int cnt = g_cnt[e];
    int m_base = blockIdx.y * BM;
    if (m_base >= cnt) return;
    int n_base = blockIdx.x * BN;

    __shared__ __align__(16) float As [BK][BM];
    __shared__ __align__(16) float B1s[BK][BN];
    __shared__ __align__(16) float B3s[BK][BN];

    int tid = threadIdx.x;
    // A (gathered x) load mapping
    int ar = tid >> 2;               // 0..63
    int ak = (tid & 3) << 2;         // 0,4,8,12
    int arow = m_base + ar;
    const float* xrow = nullptr;
    if (arow < cnt) xrow = x + (size_t)g_rowtok[e * CAP + arow] * HD;
    // B load mapping
    int bk = tid >> 4;               // 0..15
    int bn = (tid & 15) << 2;        // 0..60
    const float* w1p = w1 + ((size_t)e * HD + bk) * FF + n_base + bn;
    const float* w3p = w3 + ((size_t)e * HD + bk) * FF + n_base + bn;

    int tx = tid & 15, ty = tid >> 4;
    int n0 = tx << 2, m0 = ty << 2;
    float acc1[4][4] = {}, acc3[4][4] = {};

    for (int k0 = 0; k0 < HD; k0 += BK) {
        float4 av = xrow ? *(const float4*)(xrow + k0 + ak) : make_float4(0.f, 0.f, 0.f, 0.f);
        float4 b1 = *(const float4*)(w1p + (size_t)k0 * FF);
        float4 b3 = *(const float4*)(w3p + (size_t)k0 * FF);
        __syncthreads();
        As[ak + 0][ar] = av.x; As[ak + 1][ar] = av.y;
        As[ak + 2][ar] = av.z; As[ak + 3][ar] = av.w;
        *(float4*)&B1s[bk][bn] = b1;
        *(float4*)&B3s[bk][bn] = b3;
        __syncthreads();
        #pragma unroll
        for (int kk = 0; kk < BK; ++kk) {
            float4 a4 = *(const float4*)&As [kk][m0];
            float4 p4 = *(const float4*)&B1s[kk][n0];
            float4 q4 = *(const float4*)&B3s[kk][n0];
            float av_[4] = {a4.x, a4.y, a4.z, a4.w};
            float pv_[4] = {p4.x, p4.y, p4.z, p4.w};
            float qv_[4] = {q4.x, q4.y, q4.z, q4.w};
            #pragma unroll
            for (int i = 0; i < 4; ++i)
                #pragma unroll
                for (int j = 0; j < 4; ++j) {
                    acc1[i][j] += av_[i] * pv_[j];
                    acc3[i][j] += av_[i] * qv_[j];
                }
        }
    }
    #pragma unroll
    for (int i = 0; i < 4; ++i) {
        int r = m_base + m0 + i;
        if (r < cnt) {
            float4 o;
            float* op = (float*)&o;
            #pragma unroll
            for (int j = 0; j < 4; ++j) {
                float g = acc1[i][j], u = acc3[i][j];
                float sg = 1.f / (1.f + expf(-g));
                op[j] = g * sg * u;
            }
            *(float4*)&g_act[((size_t)e * CAP + r) * FF + n_base + n0] = o;
        }
    }
}

// ---------------- 5) GEMM-B: yb = act @ w2 ----------------
__global__ __launch_bounds__(256) void gemm_b_kernel(const float* __restrict__ w2) {
    int e = blockIdx.z;
    int cnt = g_cnt[e];
    int m_base = blockIdx.y * BM;
    if (m_base >= cnt) return;
    int n_base = blockIdx.x * BN;

    __shared__ __align__(16) float As[BK][BM];
    __shared__ __align__(16) float Bs[BK][BN];

    int tid = threadIdx.x;
    int ar = tid >> 2;
    int ak = (tid & 3) << 2;
    int arow = m_base + ar;
    const float* actrow = nullptr;
    if (arow < cnt) actrow = g_act + ((size_t)e * CAP + arow) * FF;
    int bk = tid >> 4;
    int bn = (tid & 15) << 2;
    const float* w2p = w2 + ((size_t)e * FF + bk) * HD + n_base + bn;

    int tx = tid & 15, ty = tid >> 4;
    int n0 = tx << 2, m0 = ty << 2;
    float acc[4][4] = {};

    for (int k0 = 0; k0 < FF; k0 += BK) {
        float4 av = actrow ? *(const float4*)(actrow + k0 + ak) : make_float4(0.f, 0.f, 0.f, 0.f);
        float4 bv = *(const float4*)(w2p + (size_t)k0 * HD);
        __syncthreads();
        As[ak + 0][ar] = av.x; As[ak + 1][ar] = av.y;
        As[ak + 2][ar] = av.z; As[ak + 3][ar] = av.w;
        *(float4*)&Bs[bk][bn] = bv;
        __syncthreads();
        #pragma unroll
        for (int kk = 0; kk < BK; ++kk) {
            float4 a4 = *(const float4*)&As[kk][m0];
            float4 b4 = *(const float4*)&Bs[kk][n0];
            float av_[4] = {a4.x, a4.y, a4.z, a4.w};
            float bv_[4] = {b4.x, b4.y, b4.z, b4.w};
            #pragma unroll
            for (int i = 0; i < 4; ++i)
                #pragma unroll
                for (int j = 0; j < 4; ++j)
                    acc[i][j] += av_[i] * bv_[j];
        }
    }
    #pragma unroll
    for (int i = 0; i < 4; ++i) {
        int r = m_base + m0 + i;
        if (r < cnt) {
            float4 o = make_float4(acc[i][0], acc[i][1], acc[i][2], acc[i][3]);
            *(float4*)&g_yb[((size_t)e * CAP + r) * HD + n_base + n0] = o;
        }
    }
}

// ---------------- 6) combine: out[t] = sum_k w * yb[slot(t,k)] ----------------
__global__ __launch_bounds__(256) void combine_kernel(float* __restrict__ out) {
    int t = blockIdx.x;
    int h = threadIdx.x << 2;   // 256 threads * 4 = 1024
    float4 acc = make_float4(0.f, 0.f, 0.f, 0.f);
    #pragma unroll
    for (int k = 0; k < KSEL; ++k) {
        int slot = g_slot[t * KSEL + k];
        if (slot >= 0) {
            float w = g_wgt[t * KSEL + k];
            float4 v = *(const float4*)&g_yb[(size_t)slot * HD + h];
            acc.x += w * v.x; acc.y += w * v.y;
            acc.z += w * v.z; acc.w += w * v.w;
        }
    }
    *(float4*)&out[(size_t)t * HD + h] = acc;
}

// ---------------- 7) copy router logits into output tail (if requested) ----------------
__global__ void copy_logits_kernel(float* __restrict__ dst) {
    int i = blockIdx.x * blockDim.x + threadIdx.x;
    int n = TOK * NE;
    for (; i < n; i += gridDim.x * blockDim.x) dst[i] = g_logits[i];
}

// ---------------- host launcher ----------------
extern "C" void kernel_launch(void* const* d_in, const int* in_sizes, int n_in,
                              void* d_out, int out_size) {
    const float* x  = (const float*)d_in[0];   // hidden_states [B,S,H]
    const float* wg = (const float*)d_in[1];   // w_gate [H,E]
    const float* w1 = (const float*)d_in[2];   // [E,H,F]
    const float* w3 = (const float*)d_in[3];   // [E,H,F]
    const float* w2 = (const float*)d_in[4];   // [E,F,H]
    float* out = (float*)d_out;

    router_kernel<<<TOK / RT, 256>>>(x, wg);
    topk_kernel<<<(TOK + 255) / 256, 256>>>();
    dispatch_kernel<<<NE, 256>>>();

    dim3 ga(FF / BN, CAP / BM, NE);     // (8,16,64)
    gemm_a_kernel<<<ga, 256>>>(x, w1, w3);
    dim3 gb(HD / BN, CAP / BM, NE);     // (16,16,64)
    gemm_b_kernel<<<gb, 256>>>(w2);

    combine_kernel<<<TOK, 256>>>(out);

    if ((size_t)out_size >= (size_t)TOK * HD + (size_t)TOK * NE) {
        copy_logits_kernel<<<256, 256>>>(out + (size_t)TOK * HD);
    }
}

// round 3
// speedup vs baseline: 2.0277x; 2.0277x over previous
#include <cuda_runtime.h>
#include <cuda_bf16.h>
#include <math.h>
#include <stdint.h>

// Problem constants (B=2,S=2048,H=1024,E=64,K=8,F=512,cap=2.0)
#define TOK   4096
#define HD    1024
#define NE    64
#define KSEL  8
#define FF    512
#define NA    (TOK*KSEL)
#define CAP   1024

// ---------------- scratch (__device__ globals) ----------------
__device__ __align__(16) float g_logits[(size_t)TOK * NE];
__device__ int   g_sel[NA];
__device__ float g_wgt[NA];
__device__ int   g_rowtok[NE * CAP];
__device__ float g_wslot[NE * CAP];
__device__ int   g_cnt[NE];
__device__ __align__(16) __nv_bfloat16 g_act_hi[(size_t)NE * CAP * FF];  // 64MB
__device__ __align__(16) __nv_bfloat16 g_act_lo[(size_t)NE * CAP * FF];  // 64MB

// ---------------- helpers ----------------
__device__ __forceinline__ uint32_t smem_u32(const void* p) {
    uint32_t a;
    asm("{ .reg .u64 t; cvta.to.shared.u64 t, %1; cvt.u32.u64 %0, t; }" : "=r"(a) : "l"(p));
    return a;
}
__device__ __forceinline__ void ldsm4(uint32_t* r, uint32_t addr) {
    asm volatile("ldmatrix.sync.aligned.m8n8.x4.shared.b16 {%0,%1,%2,%3}, [%4];"
                 : "=r"(r[0]), "=r"(r[1]), "=r"(r[2]), "=r"(r[3]) : "r"(addr));
}
__device__ __forceinline__ void ldsm2t(uint32_t* r, uint32_t addr) {
    asm volatile("ldmatrix.sync.aligned.m8n8.x2.trans.shared.b16 {%0,%1}, [%2];"
                 : "=r"(r[0]), "=r"(r[1]) : "r"(addr));
}
__device__ __forceinline__ void mma16816(float* c, const uint32_t* a, const uint32_t* b) {
    asm volatile("mma.sync.aligned.m16n8k16.row.col.f32.bf16.bf16.f32 "
                 "{%0,%1,%2,%3}, {%4,%5,%6,%7}, {%8,%9}, {%0,%1,%2,%3};"
                 : "+f"(c[0]), "+f"(c[1]), "+f"(c[2]), "+f"(c[3])
                 : "r"(a[0]), "r"(a[1]), "r"(a[2]), "r"(a[3]), "r"(b[0]), "r"(b[1]));
}
// split two floats into bf16x2 hi + bf16x2 lo (residual)
__device__ __forceinline__ void split2(float a, float b, uint32_t& h, uint32_t& l) {
    __nv_bfloat162 ph = __floats2bfloat162_rn(a, b);
    float ra = a - __bfloat162float(ph.x);
    float rb = b - __bfloat162float(ph.y);
    __nv_bfloat162 pl = __floats2bfloat162_rn(ra, rb);
    h = *(uint32_t*)&ph;
    l = *(uint32_t*)&pl;
}

// smem strides (elements)
#define ASTR 40   // 32 + 8 pad  (row stride 80B: banks 20r%32 distinct over 8 rows)
#define BSTR 72   // 64 + 8 pad  (row stride 144B: banks 4r%32 distinct over 8 rows)

// ---------------- 1) router logits ----------------
#define RT 8
__global__ __launch_bounds__(256) void router_kernel(const float* __restrict__ x,
                                                     const float* __restrict__ wg) {
    __shared__ __align__(16) float xs[RT][HD];
    int t0 = blockIdx.x * RT;
    for (int i = threadIdx.x; i < RT * HD / 4; i += 256) {
        int r = i >> 8;
        int c = (i & 255) << 2;
        *(float4*)&xs[r][c] = *(const float4*)&x[(size_t)(t0 + r) * HD + c];
    }
    __syncthreads();
    int e  = threadIdx.x & 63;
    int tg = threadIdx.x >> 6;
    float acc0 = 0.f, acc1 = 0.f;
#pragma unroll 4
    for (int j = 0; j < HD; ++j) {
        float w = wg[(size_t)j * NE + e];
        acc0 += w * xs[tg * 2 + 0][j];
        acc1 += w * xs[tg * 2 + 1][j];
    }
    g_logits[(size_t)(t0 + tg * 2 + 0) * NE + e] = acc0;
    g_logits[(size_t)(t0 + tg * 2 + 1) * NE + e] = acc1;
}

// ---------------- 2) softmax + top-8 + renorm ----------------
__global__ void topk_kernel() {
    int t = blockIdx.x * blockDim.x + threadIdx.x;
    if (t >= TOK) return;
    const float* l = g_logits + (size_t)t * NE;
    float m = -INFINITY;
    for (int e = 0; e < NE; ++e) m = fmaxf(m, l[e]);
    float s = 0.f;
    for (int e = 0; e < NE; ++e) s += expf(l[e] - m);
    unsigned long long mask = 0ull;
    float wv[KSEL]; int se[KSEL];
    float wsum = 0.f;
    for (int k = 0; k < KSEL; ++k) {
        float best = -INFINITY; int be = 0;
        for (int e = 0; e < NE; ++e) {
            if ((mask >> e) & 1ull) continue;
            float v = l[e];
            if (v > best) { best = v; be = e; }
        }
        mask |= (1ull << be);
        float p = expf(best - m) / s;
        wv[k] = p; se[k] = be; wsum += p;
    }
    float inv = 1.f / wsum;
    for (int k = 0; k < KSEL; ++k) {
        g_sel[t * KSEL + k] = se[k];
        g_wgt[t * KSEL + k] = wv[k] * inv;
    }
}

// ---------------- 3) dispatch: stable per-expert ranks ----------------
__global__ __launch_bounds__(256) void dispatch_kernel() {
    int e = blockIdx.x;
    __shared__ int stot[8];
    int tid = threadIdx.x, wid = tid >> 5, lane = tid & 31;
    int run = 0;
    for (int base = 0; base < NA; base += 256) {
        int a = base + tid;
        int m = (g_sel[a] == e) ? 1 : 0;
        unsigned b = __ballot_sync(0xffffffffu, m);
        int wpref = __popc(b & ((1u << lane) - 1u));
        if (lane == 0) stot[wid] = __popc(b);
        __syncthreads();
        int before = 0, total = 0;
#pragma unroll
        for (int w = 0; w < 8; ++w) {
            int c = stot[w];
            if (w < wid) before += c;
            total += c;
        }
        if (m) {
            int p = run + before + wpref;
            if (p < CAP) {
                g_rowtok[e * CAP + p] = a / KSEL;
                g_wslot[e * CAP + p]  = g_wgt[a];
            }
        }
        run += total;
        __syncthreads();
    }
    if (tid == 0) g_cnt[e] = (run < CAP) ? run : CAP;
}

// ---------------- 4) zero output ----------------
__global__ void zero_out_kernel(float4* o) {
    int i = blockIdx.x * blockDim.x + threadIdx.x;
    o[i] = make_float4(0.f, 0.f, 0.f, 0.f);
}

// ---------------- 5) GEMM-A: act = silu(x@w1)*(x@w3)  [mma.sync bf16 x3] ----------------
__global__ __launch_bounds__(256, 1) void gemm_a_mma(const float* __restrict__ x,
                                                     const float* __restrict__ w1,
                                                     const float* __restrict__ w3) {
    __shared__ __align__(16) __nv_bfloat16 Ah[128 * ASTR], Al[128 * ASTR];
    __shared__ __align__(16) __nv_bfloat16 B1h[32 * BSTR], B1l[32 * BSTR];
    __shared__ __align__(16) __nv_bfloat16 B3h[32 * BSTR], B3l[32 * BSTR];

    const int e = blockIdx.z;
    const int cnt = g_cnt[e];
    const int m_base = blockIdx.y * 128;
    if (m_base >= cnt) return;
    const int n_base = blockIdx.x * 64;

    const int tid = threadIdx.x, lane = tid & 31, wid = tid >> 5;
    const int wm = wid & 3, wn = wid >> 2;

    // --- global load mappings ---
    const int arow = tid >> 1, ahalf = tid & 1;          // A: 128 rows x 32 k
    int gr = m_base + arow; if (gr >= cnt) gr = cnt - 1;
    const float* xr = x + (size_t)g_rowtok[e * CAP + gr] * HD;
    const int bk = tid >> 3, bn0 = (tid & 7) * 8;        // B: 32 k x 64 n

    // --- smem byte bases ---
    const uint32_t sAh = smem_u32(Ah), sAl = smem_u32(Al);
    const uint32_t s1h = smem_u32(B1h), s1l = smem_u32(B1l);
    const uint32_t s3h = smem_u32(B3h), s3l = smem_u32(B3l);

    // ldmatrix per-lane offsets
    const uint32_t aoff = (uint32_t)(wm * 32 + (lane & 15)) * (ASTR * 2) + (uint32_t)(lane >> 4) * 16;
    const uint32_t boff = (uint32_t)(lane & 15) * (BSTR * 2) + (uint32_t)(wn * 32) * 2;

    float acc1[2][4][4] = {}, acc3[2][4][4] = {};
    float4 pa[4], p1[2], p3[2];

    // prefetch chunk 0
    {
        const float* w1p = w1 + ((size_t)e * HD + bk) * FF + n_base + bn0;
        const float* w3p = w3 + ((size_t)e * HD + bk) * FF + n_base + bn0;
#pragma unroll
        for (int j = 0; j < 4; ++j) pa[j] = *(const float4*)(xr + ahalf * 16 + j * 4);
#pragma unroll
        for (int q = 0; q < 2; ++q) { p1[q] = *(const float4*)(w1p + q * 4); p3[q] = *(const float4*)(w3p + q * 4); }
    }

    for (int c = 0; c < HD / 32; ++c) {
        __syncthreads();
        // store prefetched regs -> smem (hi/lo split)
        {
            uint32_t ab = (uint32_t)arow * (ASTR * 2) + (uint32_t)ahalf * 32;
#pragma unroll
            for (int j = 0; j < 4; ++j) {
                uint32_t h0, l0, h1, l1;
                split2(pa[j].x, pa[j].y, h0, l0);
                split2(pa[j].z, pa[j].w, h1, l1);
                *(uint2*)((char*)Ah + ab + j * 8) = make_uint2(h0, h1);
                *(uint2*)((char*)Al + ab + j * 8) = make_uint2(l0, l1);
            }
            uint32_t bb = (uint32_t)bk * (BSTR * 2) + (uint32_t)bn0 * 2;
            float f1[8] = {p1[0].x, p1[0].y, p1[0].z, p1[0].w, p1[1].x, p1[1].y, p1[1].z, p1[1].w};
            float f3[8] = {p3[0].x, p3[0].y, p3[0].z, p3[0].w, p3[1].x, p3[1].y, p3[1].z, p3[1].w};
            uint32_t h[4], l[4];
#pragma unroll
            for (int q = 0; q < 4; ++q) split2(f1[q * 2], f1[q * 2 + 1], h[q], l[q]);
            *(uint4*)((char*)B1h + bb) = make_uint4(h[0], h[1], h[2], h[3]);
            *(uint4*)((char*)B1l + bb) = make_uint4(l[0], l[1], l[2], l[3]);
#pragma unroll
            for (int q = 0; q < 4; ++q) split2(f3[q * 2], f3[q * 2 + 1], h[q], l[q]);
            *(uint4*)((char*)B3h + bb) = make_uint4(h[0], h[1], h[2], h[3]);
            *(uint4*)((char*)B3l + bb) = make_uint4(l[0], l[1], l[2], l[3]);
        }
        __syncthreads();
        // prefetch next chunk
        if (c + 1 < HD / 32) {
            int k0 = (c + 1) * 32;
            const float* w1p = w1 + ((size_t)e * HD + k0 + bk) * FF + n_base + bn0;
            const float* w3p = w3 + ((size_t)e * HD + k0 + bk) * FF + n_base + bn0;
#pragma unroll
            for (int j = 0; j < 4; ++j) pa[j] = *(const float4*)(xr + k0 + ahalf * 16 + j * 4);
#pragma unroll
            for (int q = 0; q < 2; ++q) { p1[q] = *(const float4*)(w1p + q * 4); p3[q] = *(const float4*)(w3p + q * 4); }
        }
        // compute: 2 k16 steps
#pragma unroll
        for (int ks = 0; ks < 2; ++ks) {
            uint32_t ah[2][4], al[2][4];
#pragma unroll
            for (int mf = 0; mf < 2; ++mf) {
                uint32_t ao = aoff + (uint32_t)mf * 16 * (ASTR * 2) + (uint32_t)ks * 32;
                ldsm4(ah[mf], sAh + ao);
                ldsm4(al[mf], sAl + ao);
            }
#pragma unroll
            for (int nf = 0; nf < 4; ++nf) {
                uint32_t bo = boff + (uint32_t)ks * 16 * (BSTR * 2) + (uint32_t)nf * 16;
                uint32_t b1h[2], b1l[2], b3h[2], b3l[2];
                ldsm2t(b1h, s1h + bo); ldsm2t(b1l, s1l + bo);
                ldsm2t(b3h, s3h + bo); ldsm2t(b3l, s3l + bo);
#pragma unroll
                for (int mf = 0; mf < 2; ++mf) {
                    mma16816(acc1[mf][nf], ah[mf], b1h);
                    mma16816(acc1[mf][nf], ah[mf], b1l);
                    mma16816(acc1[mf][nf], al[mf], b1h);
                    mma16816(acc3[mf][nf], ah[mf], b3h);
                    mma16816(acc3[mf][nf], ah[mf], b3l);
                    mma16816(acc3[mf][nf], al[mf], b3h);
                }
            }
        }
    }

    // epilogue: silu(g)*u -> bf16 hi/lo to g_act
#pragma unroll
    for (int mf = 0; mf < 2; ++mf) {
#pragma unroll
        for (int half = 0; half < 2; ++half) {
            int r = wm * 32 + mf * 16 + (lane >> 2) + half * 8;
            int grr = m_base + r;
            if (grr < cnt) {
                size_t rb = ((size_t)e * CAP + grr) * FF + n_base + wn * 32 + (lane & 3) * 2;
#pragma unroll
                for (int nf = 0; nf < 4; ++nf) {
                    float g0 = acc1[mf][nf][half * 2],     u0 = acc3[mf][nf][half * 2];
                    float g1 = acc1[mf][nf][half * 2 + 1], u1 = acc3[mf][nf][half * 2 + 1];
                    float a0 = (g0 / (1.f + expf(-g0))) * u0;
                    float a1 = (g1 / (1.f + expf(-g1))) * u1;
                    uint32_t hh, ll;
                    split2(a0, a1, hh, ll);
                    *(uint32_t*)&g_act_hi[rb + nf * 8] = hh;
                    *(uint32_t*)&g_act_lo[rb + nf * 8] = ll;
                }
            }
        }
    }
}

// ---------------- 6) GEMM-B: out += w * (act @ w2)  [mma.sync bf16 x3 + scatter] ----------------
__global__ __launch_bounds__(256, 1) void gemm_b_mma(const float* __restrict__ w2,
                                                     float* __restrict__ out) {
    __shared__ __align__(16) __nv_bfloat16 Ah[128 * ASTR], Al[128 * ASTR];
    __shared__ __align__(16) __nv_bfloat16 Bh[32 * BSTR], Bl[32 * BSTR];

    const int e = blockIdx.z;
    const int cnt = g_cnt[e];
    const int m_base = blockIdx.y * 128;
    if (m_base >= cnt) return;
    const int n_base = blockIdx.x * 64;

    const int tid = threadIdx.x, lane = tid & 31, wid = tid >> 5;
    const int wm = wid & 3, wn = wid >> 2;

    const int arow = tid >> 1, ahalf = tid & 1;
    int gr = m_base + arow; if (gr >= cnt) gr = cnt - 1;
    const __nv_bfloat16* ahp = g_act_hi + ((size_t)e * CAP + gr) * FF;
    const __nv_bfloat16* alp = g_act_lo + ((size_t)e * CAP + gr) * FF;
    const int bk = tid >> 3, bn0 = (tid & 7) * 8;

    const uint32_t sAh = smem_u32(Ah), sAl = smem_u32(Al);
    const uint32_t sBh = smem_u32(Bh), sBl = smem_u32(Bl);
    const uint32_t aoff = (uint32_t)(wm * 32 + (lane & 15)) * (ASTR * 2) + (uint32_t)(lane >> 4) * 16;
    const uint32_t boff = (uint32_t)(lane & 15) * (BSTR * 2) + (uint32_t)(wn * 32) * 2;

    float acc[2][4][4] = {};
    uint4 qh[2], ql[2];
    float4 pb[2];

    {
        const float* w2p = w2 + ((size_t)e * FF + bk) * HD + n_base + bn0;
#pragma unroll
        for (int q = 0; q < 2; ++q) {
            qh[q] = *(const uint4*)(ahp + ahalf * 16 + q * 8);
            ql[q] = *(const uint4*)(alp + ahalf * 16 + q * 8);
            pb[q] = *(const float4*)(w2p + q * 4);
        }
    }

    for (int c = 0; c < FF / 32; ++c) {
        __syncthreads();
        {
            uint32_t ab = (uint32_t)arow * (ASTR * 2) + (uint32_t)ahalf * 32;
#pragma unroll
            for (int q = 0; q < 2; ++q) {
                *(uint4*)((char*)Ah + ab + q * 16) = qh[q];
                *(uint4*)((char*)Al + ab + q * 16) = ql[q];
            }
            uint32_t bb = (uint32_t)bk * (BSTR * 2) + (uint32_t)bn0 * 2;
            float f[8] = {pb[0].x, pb[0].y, pb[0].z, pb[0].w, pb[1].x, pb[1].y, pb[1].z, pb[1].w};
            uint32_t h[4], l[4];
#pragma unroll
            for (int q = 0; q < 4; ++q) split2(f[q * 2], f[q * 2 + 1], h[q], l[q]);
            *(uint4*)((char*)Bh + bb) = make_uint4(h[0], h[1], h[2], h[3]);
            *(uint4*)((char*)Bl + bb) = make_uint4(l[0], l[1], l[2], l[3]);
        }
        __syncthreads();
        if (c + 1 < FF / 32) {
            int k0 = (c + 1) * 32;
            const float* w2p = w2 + ((size_t)e * FF + k0 + bk) * HD + n_base + bn0;
#pragma unroll
            for (int q = 0; q < 2; ++q) {
                qh[q] = *(const uint4*)(ahp + k0 + ahalf * 16 + q * 8);
                ql[q] = *(const uint4*)(alp + k0 + ahalf * 16 + q * 8);
                pb[q] = *(const float4*)(w2p + q * 4);
            }
        }
#pragma unroll
        for (int ks = 0; ks < 2; ++ks) {
            uint32_t ah[2][4], al[2][4];
#pragma unroll
            for (int mf = 0; mf < 2; ++mf) {
                uint32_t ao = aoff + (uint32_t)mf * 16 * (ASTR * 2) + (uint32_t)ks * 32;
                ldsm4(ah[mf], sAh + ao);
                ldsm4(al[mf], sAl + ao);
            }
#pragma unroll
            for (int nf = 0; nf < 4; ++nf) {
                uint32_t bo = boff + (uint32_t)ks * 16 * (BSTR * 2) + (uint32_t)nf * 16;
                uint32_t bh[2], bl[2];
                ldsm2t(bh, sBh + bo); ldsm2t(bl, sBl + bo);
#pragma unroll
                for (int mf = 0; mf < 2; ++mf) {
                    mma16816(acc[mf][nf], ah[mf], bh);
                    mma16816(acc[mf][nf], ah[mf], bl);
                    mma16816(acc[mf][nf], al[mf], bh);
                }
            }
        }
    }

    // epilogue: weighted atomic scatter to out
#pragma unroll
    for (int mf = 0; mf < 2; ++mf) {
#pragma unroll
        for (int half = 0; half < 2; ++half) {
            int r = wm * 32 + mf * 16 + (lane >> 2) + half * 8;
            int grr = m_base + r;
            if (grr < cnt) {
                int tok = g_rowtok[e * CAP + grr];
                float w  = g_wslot[e * CAP + grr];
                float* op = out + (size_t)tok * HD + n_base + wn * 32 + (lane & 3) * 2;
#pragma unroll
                for (int nf = 0; nf < 4; ++nf) {
                    atomicAdd(op + nf * 8,     w * acc[mf][nf][half * 2]);
                    atomicAdd(op + nf * 8 + 1, w * acc[mf][nf][half * 2 + 1]);
                }
            }
        }
    }
}

// ---------------- 7) copy router logits into output tail ----------------
__global__ void copy_logits_kernel(float* __restrict__ dst) {
    int i = blockIdx.x * blockDim.x + threadIdx.x;
    int n = TOK * NE;
    for (; i < n; i += gridDim.x * blockDim.x) dst[i] = g_logits[i];
}

// ---------------- host launcher ----------------
extern "C" void kernel_launch(void* const* d_in, const int* in_sizes, int n_in,
                              void* d_out, int out_size) {
    const float* x  = (const float*)d_in[0];
    const float* wg = (const float*)d_in[1];
    const float* w1 = (const float*)d_in[2];
    const float* w3 = (const float*)d_in[3];
    const float* w2 = (const float*)d_in[4];
    float* out = (float*)d_out;

    router_kernel<<<TOK / RT, 256>>>(x, wg);
    topk_kernel<<<(TOK + 255) / 256, 256>>>();
    dispatch_kernel<<<NE, 256>>>();
    zero_out_kernel<<<TOK * HD / 4 / 256, 256>>>((float4*)out);

    dim3 ga(FF / 64, CAP / 128, NE);      // (8, 8, 64)
    gemm_a_mma<<<ga, 256>>>(x, w1, w3);
    dim3 gb(HD / 64, CAP / 128, NE);      // (16, 8, 64)
    gemm_b_mma<<<gb, 256>>>(w2, out);

    if ((size_t)out_size >= (size_t)TOK * HD + (size_t)TOK * NE) {
        copy_logits_kernel<<<256, 256>>>(out + (size_t)TOK * HD);
    }
}